// round 2
// baseline (speedup 1.0000x reference)
#include <cuda_runtime.h>
#include <math.h>

// LSTM: B=64, T=512, I=H=1024. Output: h_T [64,1024] then c_T [64,1024] (fp32).
#define Bsz  64
#define Tlen 512
#define Idim 1024
#define Hdim 1024
#define G4   4096   // 4*H

// ---------------- scratch (device globals: no allocation allowed) ----------------
__device__ __align__(16) float g_xg[(size_t)Tlen * Bsz * G4];  // [t*64+b][4096] input projection (512MB)
__device__ __align__(16) float g_Wxp[(size_t)Idim * G4];       // packed Wx [k][4096]
__device__ __align__(16) float g_bsum[G4];                     // fused biases
__device__ __align__(16) float g_hbuf[2 * Bsz * Hdim];         // double-buffered h
__device__ unsigned g_bar_cnt;
__device__ unsigned g_bar_gen;

// ---------------- pack Wx gates (f,i,g,o) + biases ----------------
__global__ void pack_kernel(const float* __restrict__ Wif, const float* __restrict__ Wii,
                            const float* __restrict__ Wig, const float* __restrict__ Wio,
                            const float* __restrict__ bif_, const float* __restrict__ bhf,
                            const float* __restrict__ bii_, const float* __restrict__ bhi,
                            const float* __restrict__ big_, const float* __restrict__ bhg,
                            const float* __restrict__ bio_, const float* __restrict__ bho)
{
    int idx = blockIdx.x * blockDim.x + threadIdx.x;
    if (idx < Idim * G4) {
        int k = idx >> 12, n = idx & 4095;
        int gate = n >> 10, hid = n & 1023;
        const float* W = (gate == 0) ? Wif : (gate == 1) ? Wii : (gate == 2) ? Wig : Wio;
        g_Wxp[idx] = W[k * Hdim + hid];
    }
    if (idx < G4) {
        int gate = idx >> 10, hid = idx & 1023;
        const float* bx = (gate == 0) ? bif_ : (gate == 1) ? bii_ : (gate == 2) ? big_ : bio_;
        const float* bh = (gate == 0) ? bhf  : (gate == 1) ? bhi  : (gate == 2) ? bhg  : bho;
        g_bsum[idx] = bx[hid] + bh[hid];
    }
}

// ---------------- input projection GEMM: xg[m][n] = x_row(m) . Wxp[:,n] + bsum[n] ----------------
// m = t*64 + b  (so recurrence step t reads a contiguous [64,4096] slab)
#define BM 128
#define BN 128
#define BK 16
__global__ __launch_bounds__(256) void proj_kernel(const float* __restrict__ x)
{
    __shared__ float As[BK][BM + 4];
    __shared__ float Bs[BK][BN + 4];

    const int tid = threadIdx.x;
    const int bn0 = blockIdx.x * BN;
    const int bm0 = blockIdx.y * BM;
    const int tx = tid & 15, ty = tid >> 4;

    float acc[8][8];
#pragma unroll
    for (int i = 0; i < 8; ++i)
#pragma unroll
        for (int j = 0; j < 8; ++j) acc[i][j] = 0.f;

    for (int k0 = 0; k0 < Idim; k0 += BK) {
        // A: 128 rows x 16 k = 512 float4; 2 per thread
#pragma unroll
        for (int j = 0; j < 2; ++j) {
            int idx = tid * 2 + j;
            int am = idx >> 2;            // 0..127
            int ak = (idx & 3) * 4;       // 0,4,8,12
            int m = bm0 + am;
            int b = m & 63, t = m >> 6;
            float4 v = *(const float4*)(x + ((size_t)(b * Tlen + t)) * Idim + k0 + ak);
            As[ak + 0][am] = v.x; As[ak + 1][am] = v.y;
            As[ak + 2][am] = v.z; As[ak + 3][am] = v.w;
        }
        // B: 16 k x 128 n = 512 float4; 2 per thread
#pragma unroll
        for (int j = 0; j < 2; ++j) {
            int idx = tid * 2 + j;
            int bk = idx >> 5;            // 0..15
            int bn = (idx & 31) * 4;
            float4 v = *(const float4*)(g_Wxp + (size_t)(k0 + bk) * G4 + bn0 + bn);
            *(float4*)&Bs[bk][bn] = v;
        }
        __syncthreads();
#pragma unroll
        for (int k = 0; k < BK; ++k) {
            float a[8], bb[8];
            *(float4*)&a[0]  = *(const float4*)&As[k][ty * 8];
            *(float4*)&a[4]  = *(const float4*)&As[k][ty * 8 + 4];
            *(float4*)&bb[0] = *(const float4*)&Bs[k][tx * 8];
            *(float4*)&bb[4] = *(const float4*)&Bs[k][tx * 8 + 4];
#pragma unroll
            for (int i = 0; i < 8; ++i)
#pragma unroll
                for (int j = 0; j < 8; ++j)
                    acc[i][j] = fmaf(a[i], bb[j], acc[i][j]);
        }
        __syncthreads();
    }
    // epilogue: add fused bias, store
#pragma unroll
    for (int i = 0; i < 8; ++i) {
        size_t m = (size_t)(bm0 + ty * 8 + i);
#pragma unroll
        for (int j = 0; j < 8; j += 4) {
            int n = bn0 + tx * 8 + j;
            float4 o;
            o.x = acc[i][j + 0] + g_bsum[n + 0];
            o.y = acc[i][j + 1] + g_bsum[n + 1];
            o.z = acc[i][j + 2] + g_bsum[n + 2];
            o.w = acc[i][j + 3] + g_bsum[n + 3];
            *(float4*)(g_xg + m * G4 + n) = o;
        }
    }
}

// ---------------- persistent recurrence ----------------
// 128 CTAs, 1/SM (smem-limited) -> software grid barrier is safe.
// CTA owns hidden units [blockIdx.x*8, +8) across all 4 gates = 32 Wh columns,
// held in smem for the whole kernel. h double-buffered in global.
__device__ __forceinline__ void grid_sync(unsigned nb)
{
    __threadfence();   // every thread publishes its writes
    __syncthreads();
    if (threadIdx.x == 0) {
        unsigned gen = *(volatile unsigned*)&g_bar_gen;
        unsigned arr = atomicAdd(&g_bar_cnt, 1);
        if (arr == nb - 1) {
            g_bar_cnt = 0;
            __threadfence();
            *(volatile unsigned*)&g_bar_gen = gen + 1;
        } else {
            while (*(volatile unsigned*)&g_bar_gen == gen) { __nanosleep(32); }
        }
    }
    __syncthreads();
}

__global__ __launch_bounds__(256) void lstm_rec_kernel(
    const float* __restrict__ Whf, const float* __restrict__ Whi,
    const float* __restrict__ Whg, const float* __restrict__ Who,
    float* __restrict__ out)
{
    extern __shared__ float smn[];
    float* whs = smn;             // 1024 x 32 cols, vectorized layout: 131072 B
    float* hs  = smn + 32768;     // staged h chunk [64][128]: 32768 B

    const int tid  = threadIdx.x;
    const int lane = tid & 31, warp = tid >> 5;
    const int hbase = blockIdx.x * 8;
    const int gate = lane >> 3, hid = lane & 7;
    const unsigned NB = gridDim.x;

    // Fill Wh slice: element (k,c) -> whs[(k>>2)*128 + c*4 + (k&3)]  (float4 per (k-quad, lane))
    for (int idx = tid; idx < Hdim * 32; idx += 256) {
        int k = idx >> 5, c = idx & 31;
        int g = c >> 3, h = c & 7;
        const float* W = (g == 0) ? Whf : (g == 1) ? Whi : (g == 2) ? Whg : Who;
        whs[(k >> 2) * 128 + c * 4 + (k & 3)] = W[k * Hdim + hbase + h];
    }
    // zero h (buffer 0) for our columns
    for (int idx = tid; idx < Bsz * 8; idx += 256) {
        int r = idx >> 3, h = idx & 7;
        g_hbuf[r * Hdim + hbase + h] = 0.f;
    }
    grid_sync(NB);

    const int r0 = warp * 8;              // this warp's 8 batch rows
    const int colG = gate * 1024 + hbase + hid;
    float creg[8];
#pragma unroll
    for (int i = 0; i < 8; ++i) creg[i] = 0.f;   // c state (valid on lanes 0..7)

    for (int t = 0; t < Tlen; ++t) {
        const float* __restrict__ hrd = g_hbuf + (size_t)(t & 1) * (Bsz * Hdim);
        float*       __restrict__ hwr = g_hbuf + (size_t)((t + 1) & 1) * (Bsz * Hdim);
        const float* __restrict__ xgrow = g_xg + (size_t)t * Bsz * G4;

        float acc[8];
#pragma unroll
        for (int i = 0; i < 8; ++i) acc[i] = xgrow[(size_t)(r0 + i) * G4 + colG];

        for (int kc = 0; kc < 8; ++kc) {
            // stage h[64][128] chunk
            for (int idx = tid; idx < 64 * 32; idx += 256) {
                int r = idx >> 5, k4 = idx & 31;
                ((float4*)hs)[idx] = *(const float4*)(hrd + r * Hdim + kc * 128 + k4 * 4);
            }
            __syncthreads();
            const float4* w4 = (const float4*)whs + (kc * 32) * 32 + lane; // (kc*128/4)*32
#pragma unroll 8
            for (int kk = 0; kk < 128; kk += 4) {
                float4 wv = w4[(kk >> 2) * 32];
#pragma unroll
                for (int i = 0; i < 8; ++i) {
                    float4 hv = *(const float4*)&hs[(r0 + i) * 128 + kk];
                    acc[i] = fmaf(hv.x, wv.x, acc[i]);
                    acc[i] = fmaf(hv.y, wv.y, acc[i]);
                    acc[i] = fmaf(hv.z, wv.z, acc[i]);
                    acc[i] = fmaf(hv.w, wv.w, acc[i]);
                }
            }
            __syncthreads();
        }
        // elementwise: gates f,i,g,o live on lanes 0-7 / 8-15 / 16-23 / 24-31
#pragma unroll
        for (int i = 0; i < 8; ++i) {
            float pre = acc[i];
            float act = (gate == 2) ? tanhf(pre) : (1.f / (1.f + expf(-pre)));
            float vf = __shfl_sync(0xffffffffu, act, hid);
            float vi = __shfl_sync(0xffffffffu, act, 8 + hid);
            float vg = __shfl_sync(0xffffffffu, act, 16 + hid);
            float vo = __shfl_sync(0xffffffffu, act, 24 + hid);
            if (lane < 8) {
                int r = r0 + i;
                float cn = vf * creg[i] + vi * vg;
                creg[i] = cn;
                float hn = tanhf(cn) * vo;
                hwr[r * Hdim + hbase + hid] = hn;
                if (t == Tlen - 1) {
                    out[r * Hdim + hbase + hid] = hn;                 // h_T
                    out[Bsz * Hdim + r * Hdim + hbase + hid] = cn;    // c_T
                }
            }
        }
        grid_sync(NB);
    }
}

// ---------------- launch ----------------
extern "C" void kernel_launch(void* const* d_in, const int* in_sizes, int n_in,
                              void* d_out, int out_size)
{
    // metadata.txt order = setup_inputs() dict order:
    // 0:x, 1:W_ii, 2:W_hi, 3:W_if, 4:W_hf, 5:W_ig, 6:W_hg, 7:W_io, 8:W_ho,
    // 9:b_ii, 10:b_hi, 11:b_if, 12:b_hf, 13:b_ig, 14:b_hg, 15:b_io, 16:b_ho
    const float* x   = (const float*)d_in[0];
    const float* Wii = (const float*)d_in[1];
    const float* Whi = (const float*)d_in[2];
    const float* Wif = (const float*)d_in[3];
    const float* Whf = (const float*)d_in[4];
    const float* Wig = (const float*)d_in[5];
    const float* Whg = (const float*)d_in[6];
    const float* Wio = (const float*)d_in[7];
    const float* Who = (const float*)d_in[8];
    const float* bii = (const float*)d_in[9];
    const float* bhi = (const float*)d_in[10];
    const float* bif = (const float*)d_in[11];
    const float* bhf = (const float*)d_in[12];
    const float* big = (const float*)d_in[13];
    const float* bhg = (const float*)d_in[14];
    const float* bio = (const float*)d_in[15];
    const float* bho = (const float*)d_in[16];
    float* out = (float*)d_out;

    // 1. pack Wx + fused bias
    pack_kernel<<<(Idim * G4 + 255) / 256, 256>>>(Wif, Wii, Wig, Wio,
                                                  bif, bhf, bii, bhi,
                                                  big, bhg, bio, bho);
    // 2. input projection (depends on pack; stream-ordered)
    proj_kernel<<<dim3(G4 / BN, (Tlen * Bsz) / BM), 256>>>(x);

    // 3. persistent recurrence (Wh slice resident in smem)
    int smem_bytes = (32768 + 8192) * (int)sizeof(float);  // 163840 B
    cudaFuncSetAttribute(lstm_rec_kernel, cudaFuncAttributeMaxDynamicSharedMemorySize, smem_bytes);
    lstm_rec_kernel<<<128, 256, smem_bytes>>>(Whf, Whi, Whg, Who, out);
}

// round 4
// speedup vs baseline: 1.2012x; 1.2012x over previous
#include <cuda_runtime.h>
#include <cuda_bf16.h>
#include <math.h>
#include <stdint.h>

// LSTM: B=64, T=512, I=H=1024. Output: h_T [64,1024] then c_T [64,1024] (fp32).
#define Bsz  64
#define Tlen 512
#define Idim 1024
#define Hdim 1024
#define G4   4096   // 4*H
#define KP   3072   // 3*1024: hi/lo-split K dimension

// ---------------- scratch (device globals: no allocation allowed) ----------------
__device__ __align__(16) float         g_xg[(size_t)Tlen * Bsz * G4];   // [m][4096] input projection
__device__ __align__(16) __nv_bfloat16 g_xbf[(size_t)Tlen * Bsz * KP]; // [m][3072] A' = [x_hi|x_lo|x_hi]
__device__ __align__(16) __nv_bfloat16 g_Wbp[(size_t)G4 * KP];          // [n][3072] B' = [W_hi|W_hi|W_lo]
__device__ __align__(16) float         g_bsum[G4];                      // fused biases
__device__ __align__(16) float         g_hbuf[2 * Bsz * Hdim];          // double-buffered h
__device__ unsigned g_bar_cnt;
__device__ unsigned g_bar_gen;

// ---------------- helpers ----------------
__device__ __forceinline__ uint32_t smem_to_u32(const void* p) {
    uint32_t a;
    asm("{ .reg .u64 t; cvta.to.shared.u64 t, %1; cvt.u32.u64 %0, t; }" : "=r"(a) : "l"(p));
    return a;
}
__device__ __forceinline__ void ldsm_x4(uint32_t& r0, uint32_t& r1, uint32_t& r2, uint32_t& r3,
                                        uint32_t addr) {
    asm volatile("ldmatrix.sync.aligned.m8n8.x4.shared.b16 {%0,%1,%2,%3}, [%4];"
                 : "=r"(r0), "=r"(r1), "=r"(r2), "=r"(r3) : "r"(addr));
}
__device__ __forceinline__ void mma16816(float* c, const uint32_t* a, uint32_t b0, uint32_t b1) {
    asm volatile(
        "mma.sync.aligned.m16n8k16.row.col.f32.bf16.bf16.f32 "
        "{%0,%1,%2,%3}, {%4,%5,%6,%7}, {%8,%9}, {%0,%1,%2,%3};"
        : "+f"(c[0]), "+f"(c[1]), "+f"(c[2]), "+f"(c[3])
        : "r"(a[0]), "r"(a[1]), "r"(a[2]), "r"(a[3]), "r"(b0), "r"(b1));
}

// ---------------- pack W into bf16 hi/lo [n][3072] + fused biases ----------------
// B' sections over k' = sec*1024 + k:  sec0=W_hi, sec1=W_hi, sec2=W_lo
__global__ void packW_kernel(const float* __restrict__ Wif, const float* __restrict__ Wii,
                             const float* __restrict__ Wig, const float* __restrict__ Wio,
                             const float* __restrict__ bif_, const float* __restrict__ bhf,
                             const float* __restrict__ bii_, const float* __restrict__ bhi,
                             const float* __restrict__ big_, const float* __restrict__ bhg,
                             const float* __restrict__ bio_, const float* __restrict__ bho)
{
    size_t idx = (size_t)blockIdx.x * blockDim.x + threadIdx.x;
    if (idx < (size_t)G4 * KP) {
        int n = (int)(idx / KP), c = (int)(idx % KP);
        int sec = c >> 10, k = c & 1023;
        int gate = n >> 10, hid = n & 1023;
        const float* W = (gate == 0) ? Wif : (gate == 1) ? Wii : (gate == 2) ? Wig : Wio;
        float v = W[k * Hdim + hid];
        __nv_bfloat16 hi = __float2bfloat16(v);
        g_Wbp[idx] = (sec == 2) ? __float2bfloat16(v - __bfloat162float(hi)) : hi;
    }
    if (idx < G4) {
        int gate = (int)(idx >> 10), hid = (int)(idx & 1023);
        const float* bx = (gate == 0) ? bif_ : (gate == 1) ? bii_ : (gate == 2) ? big_ : bio_;
        const float* bh = (gate == 0) ? bhf  : (gate == 1) ? bhi  : (gate == 2) ? bhg  : bho;
        g_bsum[idx] = bx[hid] + bh[hid];
    }
}

// ---------------- x -> bf16 hi/lo [m][3072];  A' sections: sec0=x_hi, sec1=x_lo, sec2=x_hi ----------------
__global__ void xconv_kernel(const float* __restrict__ x)
{
    size_t idx = (size_t)blockIdx.x * blockDim.x + threadIdx.x;
    if (idx >= (size_t)Tlen * Bsz * KP) return;
    int m = (int)(idx / KP), c = (int)(idx % KP);
    int sec = c >> 10, k = c & 1023;
    int b = m & 63, t = m >> 6;
    float v = x[((size_t)(b * Tlen + t)) * Idim + k];
    __nv_bfloat16 hi = __float2bfloat16(v);
    g_xbf[idx] = (sec == 1) ? __float2bfloat16(v - __bfloat162float(hi)) : hi;
}

// ---------------- HMMA input-projection GEMM ----------------
// xg[m][n] = sum_k' A'[m][k'] * B'[n][k'] + bsum[n]
// CTA tile 128x128, 8 warps (2x4), warp tile 64x32, BK=32, double-buffered smem.
// smem rows padded to 40 bf16 (80B): ldmatrix 8-row access is bank-conflict-free.
#define PBK   32
#define PNCH  (KP / PBK)   // 96
#define SROW  40           // bf16 elems per smem row (80 B)

__global__ __launch_bounds__(256) void proj_mma_kernel()
{
    __shared__ __align__(16) __nv_bfloat16 sA[2][128 * SROW];
    __shared__ __align__(16) __nv_bfloat16 sB[2][128 * SROW];

    const int tid = threadIdx.x, lane = tid & 31, wid = tid >> 5;
    const int bn0 = blockIdx.x * 128, bm0 = blockIdx.y * 128;
    const int wm = wid >> 2, wn = wid & 3;          // warp grid 2x4

    const uint32_t sAb = smem_to_u32(sA);
    const uint32_t sBb = smem_to_u32(sB);
    const int rowoff = ((lane >> 3) & 1) * 8 + (lane & 7);  // ldmatrix lane row
    const int kkoff  = (lane >> 4) * 8;                     // ldmatrix lane k-half

    float acc[4][4][4];
#pragma unroll
    for (int i = 0; i < 4; ++i)
#pragma unroll
        for (int j = 0; j < 4; ++j)
#pragma unroll
            for (int r = 0; r < 4; ++r) acc[i][j][r] = 0.f;

    // loader mapping: idx = tid + q*256; row = idx>>2 (0..127), j = idx&3 (16B chunk)
    // first chunk -> buf 0
#pragma unroll
    for (int q = 0; q < 2; ++q) {
        int idx = tid + q * 256;
        int row = idx >> 2, j = idx & 3;
        *(uint4*)((char*)sA[0] + row * 80 + j * 16) =
            *(const uint4*)(g_xbf + (size_t)(bm0 + row) * KP + j * 8);
        *(uint4*)((char*)sB[0] + row * 80 + j * 16) =
            *(const uint4*)(g_Wbp + (size_t)(bn0 + row) * KP + j * 8);
    }
    __syncthreads();

    int buf = 0;
    for (int ch = 0; ch < PNCH; ++ch) {
        uint4 pa[2], pb[2];
        const bool has_next = (ch + 1 < PNCH);
        if (has_next) {
            const int kb = (ch + 1) * PBK;
#pragma unroll
            for (int q = 0; q < 2; ++q) {
                int idx = tid + q * 256;
                int row = idx >> 2, j = idx & 3;
                pa[q] = *(const uint4*)(g_xbf + (size_t)(bm0 + row) * KP + kb + j * 8);
                pb[q] = *(const uint4*)(g_Wbp + (size_t)(bn0 + row) * KP + kb + j * 8);
            }
        }
        // compute on smem[buf]
        const uint32_t aBase = sAb + buf * (128 * SROW * 2);
        const uint32_t bBase = sBb + buf * (128 * SROW * 2);
#pragma unroll
        for (int k0 = 0; k0 < PBK; k0 += 16) {
            uint32_t af[4][4], bfr[2][4];
#pragma unroll
            for (int mt = 0; mt < 4; ++mt) {
                uint32_t addr = aBase +
                    (uint32_t)(((wm * 64 + mt * 16 + rowoff) * SROW + k0 + kkoff) * 2);
                ldsm_x4(af[mt][0], af[mt][1], af[mt][2], af[mt][3], addr);
            }
#pragma unroll
            for (int pt = 0; pt < 2; ++pt) {
                uint32_t addr = bBase +
                    (uint32_t)(((wn * 32 + pt * 16 + rowoff) * SROW + k0 + kkoff) * 2);
                ldsm_x4(bfr[pt][0], bfr[pt][1], bfr[pt][2], bfr[pt][3], addr);
            }
#pragma unroll
            for (int mt = 0; mt < 4; ++mt)
#pragma unroll
                for (int nt = 0; nt < 4; ++nt) {
                    int pt = nt >> 1, hi = nt & 1;
                    mma16816(acc[mt][nt], af[mt], bfr[pt][hi], bfr[pt][hi + 2]);
                }
        }
        if (has_next) {
#pragma unroll
            for (int q = 0; q < 2; ++q) {
                int idx = tid + q * 256;
                int row = idx >> 2, j = idx & 3;
                *(uint4*)((char*)sA[buf ^ 1] + row * 80 + j * 16) = pa[q];
                *(uint4*)((char*)sB[buf ^ 1] + row * 80 + j * 16) = pb[q];
            }
        }
        __syncthreads();
        buf ^= 1;
    }

    // epilogue: C frag (m16n8): c0,c1 -> (row, col..col+1); c2,c3 -> (row+8, ..)
    const int erow = lane >> 2, ecol = (lane & 3) * 2;
#pragma unroll
    for (int mt = 0; mt < 4; ++mt)
#pragma unroll
        for (int nt = 0; nt < 4; ++nt) {
            int r = bm0 + wm * 64 + mt * 16 + erow;
            int c = bn0 + wn * 32 + nt * 8 + ecol;
            float b0 = g_bsum[c], b1 = g_bsum[c + 1];
            float2 o0 = {acc[mt][nt][0] + b0, acc[mt][nt][1] + b1};
            float2 o1 = {acc[mt][nt][2] + b0, acc[mt][nt][3] + b1};
            *(float2*)(g_xg + (size_t)r * G4 + c) = o0;
            *(float2*)(g_xg + (size_t)(r + 8) * G4 + c) = o1;
        }
}

// ---------------- persistent recurrence (unchanged from passing R2) ----------------
__device__ __forceinline__ void grid_sync(unsigned nb)
{
    __threadfence();
    __syncthreads();
    if (threadIdx.x == 0) {
        unsigned gen = *(volatile unsigned*)&g_bar_gen;
        unsigned arr = atomicAdd(&g_bar_cnt, 1);
        if (arr == nb - 1) {
            g_bar_cnt = 0;
            __threadfence();
            *(volatile unsigned*)&g_bar_gen = gen + 1;
        } else {
            while (*(volatile unsigned*)&g_bar_gen == gen) { __nanosleep(32); }
        }
    }
    __syncthreads();
}

__global__ __launch_bounds__(256) void lstm_rec_kernel(
    const float* __restrict__ Whf, const float* __restrict__ Whi,
    const float* __restrict__ Whg, const float* __restrict__ Who,
    float* __restrict__ out)
{
    extern __shared__ float smn[];
    float* whs = smn;             // 1024 x 32 cols: 131072 B
    float* hs  = smn + 32768;     // staged h chunk [64][128]: 32768 B

    const int tid  = threadIdx.x;
    const int lane = tid & 31, warp = tid >> 5;
    const int hbase = blockIdx.x * 8;
    const int gate = lane >> 3, hid = lane & 7;
    const unsigned NB = gridDim.x;

    for (int idx = tid; idx < Hdim * 32; idx += 256) {
        int k = idx >> 5, c = idx & 31;
        int g = c >> 3, h = c & 7;
        const float* W = (g == 0) ? Whf : (g == 1) ? Whi : (g == 2) ? Whg : Who;
        whs[(k >> 2) * 128 + c * 4 + (k & 3)] = W[k * Hdim + hbase + h];
    }
    for (int idx = tid; idx < Bsz * 8; idx += 256) {
        int r = idx >> 3, h = idx & 7;
        g_hbuf[r * Hdim + hbase + h] = 0.f;
    }
    grid_sync(NB);

    const int r0 = warp * 8;
    const int colG = gate * 1024 + hbase + hid;
    float creg[8];
#pragma unroll
    for (int i = 0; i < 8; ++i) creg[i] = 0.f;

    for (int t = 0; t < Tlen; ++t) {
        const float* __restrict__ hrd = g_hbuf + (size_t)(t & 1) * (Bsz * Hdim);
        float*       __restrict__ hwr = g_hbuf + (size_t)((t + 1) & 1) * (Bsz * Hdim);
        const float* __restrict__ xgrow = g_xg + (size_t)t * Bsz * G4;

        float acc[8];
#pragma unroll
        for (int i = 0; i < 8; ++i) acc[i] = xgrow[(size_t)(r0 + i) * G4 + colG];

        for (int kc = 0; kc < 8; ++kc) {
            for (int idx = tid; idx < 64 * 32; idx += 256) {
                int r = idx >> 5, k4 = idx & 31;
                ((float4*)hs)[idx] = *(const float4*)(hrd + r * Hdim + kc * 128 + k4 * 4);
            }
            __syncthreads();
            const float4* w4 = (const float4*)whs + (kc * 32) * 32 + lane;
#pragma unroll 8
            for (int kk = 0; kk < 128; kk += 4) {
                float4 wv = w4[(kk >> 2) * 32];
#pragma unroll
                for (int i = 0; i < 8; ++i) {
                    float4 hv = *(const float4*)&hs[(r0 + i) * 128 + kk];
                    acc[i] = fmaf(hv.x, wv.x, acc[i]);
                    acc[i] = fmaf(hv.y, wv.y, acc[i]);
                    acc[i] = fmaf(hv.z, wv.z, acc[i]);
                    acc[i] = fmaf(hv.w, wv.w, acc[i]);
                }
            }
            __syncthreads();
        }
#pragma unroll
        for (int i = 0; i < 8; ++i) {
            float pre = acc[i];
            float act = (gate == 2) ? tanhf(pre) : (1.f / (1.f + expf(-pre)));
            float vf = __shfl_sync(0xffffffffu, act, hid);
            float vi = __shfl_sync(0xffffffffu, act, 8 + hid);
            float vg = __shfl_sync(0xffffffffu, act, 16 + hid);
            float vo = __shfl_sync(0xffffffffu, act, 24 + hid);
            if (lane < 8) {
                int r = r0 + i;
                float cn = vf * creg[i] + vi * vg;
                creg[i] = cn;
                float hn = tanhf(cn) * vo;
                hwr[r * Hdim + hbase + hid] = hn;
                if (t == Tlen - 1) {
                    out[r * Hdim + hbase + hid] = hn;                 // h_T
                    out[Bsz * Hdim + r * Hdim + hbase + hid] = cn;    // c_T
                }
            }
        }
        grid_sync(NB);
    }
}

// ---------------- launch ----------------
extern "C" void kernel_launch(void* const* d_in, const int* in_sizes, int n_in,
                              void* d_out, int out_size)
{
    // metadata order = setup_inputs() dict order:
    // 0:x, 1:W_ii, 2:W_hi, 3:W_if, 4:W_hf, 5:W_ig, 6:W_hg, 7:W_io, 8:W_ho,
    // 9:b_ii, 10:b_hi, 11:b_if, 12:b_hf, 13:b_ig, 14:b_hg, 15:b_io, 16:b_ho
    const float* x   = (const float*)d_in[0];
    const float* Wii = (const float*)d_in[1];
    const float* Whi = (const float*)d_in[2];
    const float* Wif = (const float*)d_in[3];
    const float* Whf = (const float*)d_in[4];
    const float* Wig = (const float*)d_in[5];
    const float* Whg = (const float*)d_in[6];
    const float* Wio = (const float*)d_in[7];
    const float* Who = (const float*)d_in[8];
    const float* bii = (const float*)d_in[9];
    const float* bhi = (const float*)d_in[10];
    const float* bif = (const float*)d_in[11];
    const float* bhf = (const float*)d_in[12];
    const float* big = (const float*)d_in[13];
    const float* bhg = (const float*)d_in[14];
    const float* bio = (const float*)d_in[15];
    const float* bho = (const float*)d_in[16];
    float* out = (float*)d_out;

    // 1. pack W (bf16 hi/lo, [n][k']) + fused biases
    {
        size_t tot = (size_t)G4 * KP;
        packW_kernel<<<(unsigned)((tot + 255) / 256), 256>>>(Wif, Wii, Wig, Wio,
                                                             bif, bhf, bii, bhi,
                                                             big, bhg, bio, bho);
    }
    // 2. x -> bf16 hi/lo [m][k']
    {
        size_t tot = (size_t)Tlen * Bsz * KP;
        xconv_kernel<<<(unsigned)((tot + 255) / 256), 256>>>(x);
    }
    // 3. HMMA input projection
    proj_mma_kernel<<<dim3(G4 / 128, (Tlen * Bsz) / 128), 256>>>();

    // 4. persistent recurrence (Wh resident in smem)
    {
        int smem_bytes = (32768 + 8192) * (int)sizeof(float);  // 163840
        cudaFuncSetAttribute(lstm_rec_kernel, cudaFuncAttributeMaxDynamicSharedMemorySize, smem_bytes);
        lstm_rec_kernel<<<128, 256, smem_bytes>>>(Whf, Whi, Whg, Who, out);
    }
}

// round 5
// speedup vs baseline: 1.3275x; 1.1051x over previous
#include <cuda_runtime.h>
#include <cuda_bf16.h>
#include <math.h>
#include <stdint.h>

// LSTM: B=64, T=512, I=H=1024. Output: h_T [64,1024] then c_T [64,1024] (fp32).
#define Bsz  64
#define Tlen 512
#define Idim 1024
#define Hdim 1024
#define G4   4096   // 4*H
#define KP   3072   // 3*1024: hi/lo-split K dimension

// ---------------- scratch (device globals: no allocation allowed) ----------------
// g_xg layout: [cta 128][t 512][row 64][32 cols(gate*8+unit)]  (gates f,i,g,o)
__device__ __align__(16) float         g_xg[(size_t)Tlen * Bsz * G4];
__device__ __align__(16) __nv_bfloat16 g_xbf[(size_t)Tlen * Bsz * KP]; // [m][3072] A'=[x_hi|x_lo|x_hi]
__device__ __align__(16) __nv_bfloat16 g_Wbp[(size_t)G4 * KP];          // [n][3072] B'=[W_hi|W_hi|W_lo]
__device__ __align__(16) float         g_bsum[G4];                      // fused biases
__device__ __align__(16) __nv_bfloat16 g_hA[2 * 64 * 2048];             // h' double buf: [row][h_hi(1024)|h_lo(1024)]
__device__ unsigned g_bar_cnt;
__device__ unsigned g_bar_gen;

// ---------------- helpers ----------------
__device__ __forceinline__ uint32_t smem_to_u32(const void* p) {
    uint32_t a;
    asm("{ .reg .u64 t; cvta.to.shared.u64 t, %1; cvt.u32.u64 %0, t; }" : "=r"(a) : "l"(p));
    return a;
}
__device__ __forceinline__ void ldsm_x4(uint32_t& r0, uint32_t& r1, uint32_t& r2, uint32_t& r3,
                                        uint32_t addr) {
    asm volatile("ldmatrix.sync.aligned.m8n8.x4.shared.b16 {%0,%1,%2,%3}, [%4];"
                 : "=r"(r0), "=r"(r1), "=r"(r2), "=r"(r3) : "r"(addr));
}
__device__ __forceinline__ void mma16816(float* c, const uint32_t* a, uint32_t b0, uint32_t b1) {
    asm volatile(
        "mma.sync.aligned.m16n8k16.row.col.f32.bf16.bf16.f32 "
        "{%0,%1,%2,%3}, {%4,%5,%6,%7}, {%8,%9}, {%0,%1,%2,%3};"
        : "+f"(c[0]), "+f"(c[1]), "+f"(c[2]), "+f"(c[3])
        : "r"(a[0]), "r"(a[1]), "r"(a[2]), "r"(a[3]), "r"(b0), "r"(b1));
}
__device__ __forceinline__ float sigf(float x) { return 1.f / (1.f + __expf(-x)); }

// ---------------- pack W into bf16 hi/lo [n][3072] + fused biases ----------------
__global__ void packW_kernel(const float* __restrict__ Wif, const float* __restrict__ Wii,
                             const float* __restrict__ Wig, const float* __restrict__ Wio,
                             const float* __restrict__ bif_, const float* __restrict__ bhf,
                             const float* __restrict__ bii_, const float* __restrict__ bhi,
                             const float* __restrict__ big_, const float* __restrict__ bhg,
                             const float* __restrict__ bio_, const float* __restrict__ bho)
{
    size_t idx = (size_t)blockIdx.x * blockDim.x + threadIdx.x;
    if (idx < (size_t)G4 * KP) {
        int n = (int)(idx / KP), c = (int)(idx % KP);
        int sec = c >> 10, k = c & 1023;
        int gate = n >> 10, hid = n & 1023;
        const float* W = (gate == 0) ? Wif : (gate == 1) ? Wii : (gate == 2) ? Wig : Wio;
        float v = W[k * Hdim + hid];
        __nv_bfloat16 hi = __float2bfloat16(v);
        g_Wbp[idx] = (sec == 2) ? __float2bfloat16(v - __bfloat162float(hi)) : hi;
    }
    if (idx < G4) {
        int gate = (int)(idx >> 10), hid = (int)(idx & 1023);
        const float* bx = (gate == 0) ? bif_ : (gate == 1) ? bii_ : (gate == 2) ? big_ : bio_;
        const float* bh = (gate == 0) ? bhf  : (gate == 1) ? bhi  : (gate == 2) ? bhg  : bho;
        g_bsum[idx] = bx[hid] + bh[hid];
    }
}

// ---------------- x -> bf16 hi/lo [m][3072] ----------------
__global__ void xconv_kernel(const float* __restrict__ x)
{
    size_t idx = (size_t)blockIdx.x * blockDim.x + threadIdx.x;
    if (idx >= (size_t)Tlen * Bsz * KP) return;
    int m = (int)(idx / KP), c = (int)(idx % KP);
    int sec = c >> 10, k = c & 1023;
    int b = m & 63, t = m >> 6;
    float v = x[((size_t)(b * Tlen + t)) * Idim + k];
    __nv_bfloat16 hi = __float2bfloat16(v);
    g_xbf[idx] = (sec == 1) ? __float2bfloat16(v - __bfloat162float(hi)) : hi;
}

// ---------------- HMMA input-projection GEMM (writes rec-friendly xg layout) ----------------
#define PBK   32
#define PNCH  (KP / PBK)   // 96
#define SROW  40           // bf16 elems per smem row (80 B)

__global__ __launch_bounds__(256) void proj_mma_kernel()
{
    __shared__ __align__(16) __nv_bfloat16 sA[2][128 * SROW];
    __shared__ __align__(16) __nv_bfloat16 sB[2][128 * SROW];

    const int tid = threadIdx.x, lane = tid & 31, wid = tid >> 5;
    const int bn0 = blockIdx.x * 128, bm0 = blockIdx.y * 128;
    const int wm = wid >> 2, wn = wid & 3;          // warp grid 2x4

    const uint32_t sAb = smem_to_u32(sA);
    const uint32_t sBb = smem_to_u32(sB);
    const int rowoff = ((lane >> 3) & 1) * 8 + (lane & 7);
    const int kkoff  = (lane >> 4) * 8;

    float acc[4][4][4];
#pragma unroll
    for (int i = 0; i < 4; ++i)
#pragma unroll
        for (int j = 0; j < 4; ++j)
#pragma unroll
            for (int r = 0; r < 4; ++r) acc[i][j][r] = 0.f;

#pragma unroll
    for (int q = 0; q < 2; ++q) {
        int idx = tid + q * 256;
        int row = idx >> 2, j = idx & 3;
        *(uint4*)((char*)sA[0] + row * 80 + j * 16) =
            *(const uint4*)(g_xbf + (size_t)(bm0 + row) * KP + j * 8);
        *(uint4*)((char*)sB[0] + row * 80 + j * 16) =
            *(const uint4*)(g_Wbp + (size_t)(bn0 + row) * KP + j * 8);
    }
    __syncthreads();

    int buf = 0;
    for (int ch = 0; ch < PNCH; ++ch) {
        uint4 pa[2], pb[2];
        const bool has_next = (ch + 1 < PNCH);
        if (has_next) {
            const int kb = (ch + 1) * PBK;
#pragma unroll
            for (int q = 0; q < 2; ++q) {
                int idx = tid + q * 256;
                int row = idx >> 2, j = idx & 3;
                pa[q] = *(const uint4*)(g_xbf + (size_t)(bm0 + row) * KP + kb + j * 8);
                pb[q] = *(const uint4*)(g_Wbp + (size_t)(bn0 + row) * KP + kb + j * 8);
            }
        }
        const uint32_t aBase = sAb + buf * (128 * SROW * 2);
        const uint32_t bBase = sBb + buf * (128 * SROW * 2);
#pragma unroll
        for (int k0 = 0; k0 < PBK; k0 += 16) {
            uint32_t af[4][4], bfr[2][4];
#pragma unroll
            for (int mt = 0; mt < 4; ++mt) {
                uint32_t addr = aBase +
                    (uint32_t)(((wm * 64 + mt * 16 + rowoff) * SROW + k0 + kkoff) * 2);
                ldsm_x4(af[mt][0], af[mt][1], af[mt][2], af[mt][3], addr);
            }
#pragma unroll
            for (int pt = 0; pt < 2; ++pt) {
                uint32_t addr = bBase +
                    (uint32_t)(((wn * 32 + pt * 16 + rowoff) * SROW + k0 + kkoff) * 2);
                ldsm_x4(bfr[pt][0], bfr[pt][1], bfr[pt][2], bfr[pt][3], addr);
            }
#pragma unroll
            for (int mt = 0; mt < 4; ++mt)
#pragma unroll
                for (int nt = 0; nt < 4; ++nt) {
                    int pt = nt >> 1, hi = nt & 1;
                    mma16816(acc[mt][nt], af[mt], bfr[pt][hi], bfr[pt][hi + 2]);
                }
        }
        if (has_next) {
#pragma unroll
            for (int q = 0; q < 2; ++q) {
                int idx = tid + q * 256;
                int row = idx >> 2, j = idx & 3;
                *(uint4*)((char*)sA[buf ^ 1] + row * 80 + j * 16) = pa[q];
                *(uint4*)((char*)sB[buf ^ 1] + row * 80 + j * 16) = pb[q];
            }
        }
        __syncthreads();
        buf ^= 1;
    }

    // epilogue -> xg layout [cta][t][row][gate*8+unit], bias folded in
    const int erow = lane >> 2, ecol = (lane & 3) * 2;
#pragma unroll
    for (int mt = 0; mt < 4; ++mt)
#pragma unroll
        for (int nt = 0; nt < 4; ++nt) {
            int r = bm0 + wm * 64 + mt * 16 + erow;           // m = t*64 + b
            int c = bn0 + wn * 32 + nt * 8 + ecol;
            int tt = r >> 6, b = r & 63;
            int gate = c >> 10, cc = c & 1023, ctaId = cc >> 3, unit = cc & 7;
            size_t base = (size_t)ctaId * (512 * 64 * 32) + (size_t)tt * 2048 + b * 32 + gate * 8 + unit;
            float b0 = g_bsum[c], b1 = g_bsum[c + 1];
            float2 o0 = {acc[mt][nt][0] + b0, acc[mt][nt][1] + b1};
            float2 o1 = {acc[mt][nt][2] + b0, acc[mt][nt][3] + b1};
            *(float2*)(g_xg + base) = o0;            // row b
            *(float2*)(g_xg + base + 8 * 32) = o1;   // row b+8
        }
}

// ---------------- grid barrier ----------------
__device__ __forceinline__ void grid_sync(unsigned nb)
{
    __threadfence();
    __syncthreads();
    if (threadIdx.x == 0) {
        unsigned gen = *(volatile unsigned*)&g_bar_gen;
        unsigned arr = atomicAdd(&g_bar_cnt, 1);
        if (arr == nb - 1) {
            g_bar_cnt = 0;
            __threadfence();
            *(volatile unsigned*)&g_bar_gen = gen + 1;
        } else {
            while (*(volatile unsigned*)&g_bar_gen == gen) { __nanosleep(32); }
        }
    }
    __syncthreads();
}

// ---------------- HMMA persistent recurrence ----------------
// 128 CTAs. CTA owns 8 hidden units x 4 gates = 32 Wh' columns resident in smem
// ([32][3072] bf16, pitch 3080 -> conflict-free ldmatrix). h' (hi|lo bf16) double-
// buffered in global; 3rd split term reuses h_hi (kphys = k' & 2047).
// Warps: wid&3 = m-tile (16 rows), wid>>2 = K-half (1536). smem reduction between halves.
#define BPITCH 3080
__global__ __launch_bounds__(256) void lstm_rec_mma(
    const float* __restrict__ Whf, const float* __restrict__ Whi,
    const float* __restrict__ Whg, const float* __restrict__ Who,
    float* __restrict__ out)
{
    extern __shared__ __align__(16) char sm[];
    __nv_bfloat16* Bs = (__nv_bfloat16*)sm;          // 32 * 3080 * 2B = 197120
    float* red = (float*)(sm + 32 * BPITCH * 2);     // 4*16*32 fp32 = 8192

    const int tid = threadIdx.x, lane = tid & 31, wid = tid >> 5;
    const int cta = blockIdx.x;
    const int mt = wid & 3, kh = wid >> 2;
    const unsigned NB = gridDim.x;

    // fill Wh' slice: sec0,1 = hi, sec2 = lo
    for (int idx = tid; idx < 32 * 1024; idx += 256) {
        int c = idx >> 10, k = idx & 1023;
        int g = c >> 3, u = c & 7;
        const float* W = (g == 0) ? Whf : (g == 1) ? Whi : (g == 2) ? Whg : Who;
        float v = W[k * Hdim + cta * 8 + u];
        __nv_bfloat16 hi = __float2bfloat16(v);
        __nv_bfloat16 lo = __float2bfloat16(v - __bfloat162float(hi));
        Bs[c * BPITCH + k] = hi;
        Bs[c * BPITCH + 1024 + k] = hi;
        Bs[c * BPITCH + 2048 + k] = lo;
    }
    // zero h buf0 (grid-wide cooperative)
    for (int idx = cta * 256 + tid; idx < 64 * 2048 / 2; idx += 128 * 256)
        ((uint32_t*)g_hA)[idx] = 0u;
    grid_sync(NB);

    const uint32_t Bbase = smem_to_u32(Bs);
    const int rowoff = ((lane >> 3) & 1) * 8 + (lane & 7);
    const int kkoff  = (lane >> 4) * 8;
    const int arow   = mt * 16 + (lane >> 2);
    const int uu     = (lane & 3) * 2;
    const size_t ctaSlab = (size_t)cta * (512 * 64 * 32);

    float cf[4] = {0.f, 0.f, 0.f, 0.f};  // c state (kh0 lanes): [row-half][unit]

    for (int t = 0; t < Tlen; ++t) {
        const __nv_bfloat16* __restrict__ hA = g_hA + (size_t)(t & 1) * (64 * 2048);
        const __nv_bfloat16* __restrict__ aptr = hA + arow * 2048 + uu;

        float acc[4][4];
#pragma unroll
        for (int i = 0; i < 4; ++i)
#pragma unroll
            for (int j = 0; j < 4; ++j) acc[i][j] = 0.f;

        const int kb = kh * 1536;
#pragma unroll 4
        for (int s = 0; s < 96; ++s) {
            const int kp = kb + s * 16;           // k' in [0,3072)
            const int kphys = kp & 2047;          // A' physical (h_hi reused for sec2)
            uint32_t av[4];
            av[0] = *(const uint32_t*)(aptr + kphys);
            av[1] = *(const uint32_t*)(aptr + kphys + 8 * 2048);
            av[2] = *(const uint32_t*)(aptr + kphys + 8);
            av[3] = *(const uint32_t*)(aptr + kphys + 8 * 2048 + 8);
#pragma unroll
            for (int pt = 0; pt < 2; ++pt) {
                uint32_t bb[4];
                uint32_t addr = Bbase +
                    (uint32_t)(((pt * 16 + rowoff) * BPITCH + kp + kkoff) * 2);
                ldsm_x4(bb[0], bb[1], bb[2], bb[3], addr);
                mma16816(acc[pt * 2 + 0], av, bb[0], bb[2]);
                mma16816(acc[pt * 2 + 1], av, bb[1], bb[3]);
            }
        }

        if (kh == 1) {
#pragma unroll
            for (int nt = 0; nt < 4; ++nt) {
                int base = mt * 512 + (lane >> 2) * 32 + nt * 8 + uu;
                *(float2*)&red[base]       = make_float2(acc[nt][0], acc[nt][1]);
                *(float2*)&red[base + 256] = make_float2(acc[nt][2], acc[nt][3]);
            }
        }
        __syncthreads();
        if (kh == 0) {
            float p[4][4];
#pragma unroll
            for (int nt = 0; nt < 4; ++nt) {
                int base = mt * 512 + (lane >> 2) * 32 + nt * 8 + uu;
                float2 r1 = *(float2*)&red[base];
                float2 r2 = *(float2*)&red[base + 256];
                const float* xg0 = g_xg + ctaSlab + (size_t)t * 2048 + arow * 32 + nt * 8 + uu;
                float2 x1 = *(const float2*)xg0;
                float2 x2 = *(const float2*)(xg0 + 256);
                p[nt][0] = acc[nt][0] + r1.x + x1.x;
                p[nt][1] = acc[nt][1] + r1.y + x1.y;
                p[nt][2] = acc[nt][2] + r2.x + x2.x;
                p[nt][3] = acc[nt][3] + r2.y + x2.y;
            }
            __nv_bfloat16* hw = g_hA + (size_t)((t + 1) & 1) * (64 * 2048);
#pragma unroll
            for (int j = 0; j < 2; ++j) {          // row-half: arow, arow+8
                float hn[2];
#pragma unroll
                for (int q = 0; q < 2; ++q) {      // unit: uu, uu+1
                    float f  = sigf(p[0][j * 2 + q]);
                    float ii = sigf(p[1][j * 2 + q]);
                    float gg = tanhf(p[2][j * 2 + q]);
                    float oo = sigf(p[3][j * 2 + q]);
                    float cn = f * cf[j * 2 + q] + ii * gg;
                    cf[j * 2 + q] = cn;
                    hn[q] = tanhf(cn) * oo;
                }
                int row = arow + j * 8;
                __nv_bfloat16 h0 = __float2bfloat16(hn[0]);
                __nv_bfloat16 h1 = __float2bfloat16(hn[1]);
                __nv_bfloat16 l0 = __float2bfloat16(hn[0] - __bfloat162float(h0));
                __nv_bfloat16 l1 = __float2bfloat16(hn[1] - __bfloat162float(h1));
                uint32_t hp = (uint32_t)__bfloat16_as_ushort(h0) |
                              ((uint32_t)__bfloat16_as_ushort(h1) << 16);
                uint32_t lp = (uint32_t)__bfloat16_as_ushort(l0) |
                              ((uint32_t)__bfloat16_as_ushort(l1) << 16);
                *(uint32_t*)(hw + row * 2048 + cta * 8 + uu) = hp;
                *(uint32_t*)(hw + row * 2048 + 1024 + cta * 8 + uu) = lp;
                if (t == Tlen - 1) {
                    *(float2*)(out + row * 1024 + cta * 8 + uu) = make_float2(hn[0], hn[1]);
                    *(float2*)(out + 65536 + row * 1024 + cta * 8 + uu) =
                        make_float2(cf[j * 2 + 0], cf[j * 2 + 1]);
                }
            }
        }
        grid_sync(NB);
    }
}

// ---------------- launch ----------------
extern "C" void kernel_launch(void* const* d_in, const int* in_sizes, int n_in,
                              void* d_out, int out_size)
{
    // metadata order = setup_inputs() dict order:
    // 0:x, 1:W_ii, 2:W_hi, 3:W_if, 4:W_hf, 5:W_ig, 6:W_hg, 7:W_io, 8:W_ho,
    // 9:b_ii, 10:b_hi, 11:b_if, 12:b_hf, 13:b_ig, 14:b_hg, 15:b_io, 16:b_ho
    const float* x   = (const float*)d_in[0];
    const float* Wii = (const float*)d_in[1];
    const float* Whi = (const float*)d_in[2];
    const float* Wif = (const float*)d_in[3];
    const float* Whf = (const float*)d_in[4];
    const float* Wig = (const float*)d_in[5];
    const float* Whg = (const float*)d_in[6];
    const float* Wio = (const float*)d_in[7];
    const float* Who = (const float*)d_in[8];
    const float* bii = (const float*)d_in[9];
    const float* bhi = (const float*)d_in[10];
    const float* bif = (const float*)d_in[11];
    const float* bhf = (const float*)d_in[12];
    const float* big = (const float*)d_in[13];
    const float* bhg = (const float*)d_in[14];
    const float* bio = (const float*)d_in[15];
    const float* bho = (const float*)d_in[16];
    float* out = (float*)d_out;

    // 1. pack W (bf16 hi/lo) + fused biases
    {
        size_t tot = (size_t)G4 * KP;
        packW_kernel<<<(unsigned)((tot + 255) / 256), 256>>>(Wif, Wii, Wig, Wio,
                                                             bif, bhf, bii, bhi,
                                                             big, bhg, bio, bho);
    }
    // 2. x -> bf16 hi/lo
    {
        size_t tot = (size_t)Tlen * Bsz * KP;
        xconv_kernel<<<(unsigned)((tot + 255) / 256), 256>>>(x);
    }
    // 3. HMMA input projection
    proj_mma_kernel<<<dim3(G4 / 128, (Tlen * Bsz) / 128), 256>>>();

    // 4. HMMA persistent recurrence
    {
        int smem_bytes = 32 * BPITCH * 2 + 4 * 16 * 32 * 4;  // 197120 + 8192 = 205312
        cudaFuncSetAttribute(lstm_rec_mma, cudaFuncAttributeMaxDynamicSharedMemorySize, smem_bytes);
        lstm_rec_mma<<<128, 256, smem_bytes>>>(Whf, Whi, Whg, Who, out);
    }
}